// round 3
// baseline (speedup 1.0000x reference)
#include <cuda_runtime.h>

#define BB 16
#define NN 2048
#define CC 256
#define RR 128
#define KK 16

// ---------------- scratch (device globals; no runtime allocation) ----------------
__device__ float g_x1 [BB*RR*NN];          // mlp1 out -> post-BN x
__device__ float g_x2 [BB*RR*NN];          // DSgroup out x (then x+t)
__device__ float g_h  [BB*RR*NN*8];        // DSgroup pre-BN   (134 MB)
__device__ float g_lap[BB*NN*RR];          // laplacian [B,N,R]
__device__ float g_t  [BB*RR*NN];          // lu pre-BN
__device__ float g_y  [BB*CC*NN];          // mlp2 pre-BN -> y
__device__ int   g_idx[BB*NN*KK];          // knn top-16 (sorted)
__device__ float g_scale[512];
__device__ float g_shift[512];

// ---------------- kNN: top-16 by (dist, index), stable ---------------------------
// Bit-exact emulation of the reference pipeline:
//   inner = GEMM K=2 fma chain:  fma(x1n, x1m, rn(x0n*x0m))
//   xx    = rn(rn(x0^2) + rn(x1^2))            (mul HLO then reduce-add HLO)
//   dist  = rn(rn(xx_n - rn(2*inner)) + xx_m)  (separate elementwise HLOs)
__global__ void __launch_bounds__(256) knn_kernel(const float* __restrict__ xyz,
                                                  int* __restrict__ idx) {
    int b  = blockIdx.x >> 3;
    int q0 = (blockIdx.x & 7) << 8;
    __shared__ float sx[NN], sy[NN], sxx[NN];
    const float* bx = xyz + (size_t)b * 3 * NN;
    for (int i = threadIdx.x; i < NN; i += 256) {
        float xv = bx[i], yv = bx[NN + i];
        sx[i] = xv; sy[i] = yv;
        sxx[i] = __fadd_rn(__fmul_rn(xv, xv), __fmul_rn(yv, yv));
    }
    __syncthreads();
    int q = q0 + threadIdx.x;
    float xq = sx[q], yq = sy[q];
    float xxq = sxx[q];
    float bd[KK]; int bi[KK];
#pragma unroll
    for (int i = 0; i < KK; i++) { bd[i] = 3.4e38f; bi[i] = 0; }
    for (int m = 0; m < NN; m++) {
        float inner = __fmaf_rn(yq, sy[m], __fmul_rn(xq, sx[m]));  // k-ascending fma chain
        float d = __fadd_rn(__fsub_rn(xxq, __fmul_rn(2.0f, inner)), sxx[m]);
        if (d < bd[KK - 1]) {
            int pos = KK - 1;
            while (pos > 0 && d < bd[pos - 1]) {         // strict < => stable ties
                bd[pos] = bd[pos - 1]; bi[pos] = bi[pos - 1]; --pos;
            }
            bd[pos] = d; bi[pos] = m;
        }
    }
    int* o = idx + ((size_t)(b * NN + q)) * KK;
#pragma unroll
    for (int i = 0; i < KK; i++) o[i] = bi[i];
}

// ---------------- generic tiled SGEMM: OUT[b,o,q] = W[o,:] . IN[b,:,col(q)] + bias ----
// MODE 0: IN is [B, I, NIN], col(q)=q
// MODE 1: IN is [B, I, NIN], col(q)=gather src (DSgroup scramble)
// MODE 2: IN is [B, QOUT, I] (transposed positions-major, laplacian)
template<int O, int I, int QOUT, int NIN, int MODE>
__global__ void __launch_bounds__(256) gemm_kernel(const float* __restrict__ IN,
                                                   const float* __restrict__ W,
                                                   const float* __restrict__ bias,
                                                   float* __restrict__ OUT,
                                                   const int* __restrict__ gidx) {
    __shared__ float sA[8][128];
    __shared__ float sB[8][128];
    __shared__ int   sSrc[128];
    int b  = blockIdx.z;
    int q0 = blockIdx.x * 128;
    int o0 = blockIdx.y * 128;
    int tid = threadIdx.x;

    if (MODE == 1) {
        if (tid < 128) {
            int qg = q0 + tid;
            int n2 = qg >> 3, j2 = qg & 7;
            int p  = j2 * NN + n2;                        // scrambled view position
            sSrc[tid] = gidx[((size_t)(b * NN + (p >> 3)) << 4) + (p & 7)];
        }
        __syncthreads();
    }

    float acc[8][8];
#pragma unroll
    for (int i = 0; i < 8; i++)
#pragma unroll
        for (int j = 0; j < 8; j++) acc[i][j] = 0.f;

    int tx = tid & 15, ty = tid >> 4;

    for (int kb = 0; kb < I; kb += 8) {
        {   // A tile: sA[i][o] <- W[o0+o, kb+i]
            int o = tid >> 1, i4 = (tid & 1) * 4;
            float4 v = *(const float4*)(W + (size_t)(o0 + o) * I + kb + i4);
            sA[i4 + 0][o] = v.x; sA[i4 + 1][o] = v.y;
            sA[i4 + 2][o] = v.z; sA[i4 + 3][o] = v.w;
        }
        if (MODE == 0) {
            int i = tid >> 5, q4 = (tid & 31) * 4;
            float4 v = *(const float4*)(IN + ((size_t)(b * I + kb + i)) * NIN + q0 + q4);
            *(float4*)&sB[i][q4] = v;
        } else if (MODE == 1) {
            int i = tid >> 5, q4 = (tid & 31) * 4;
            const float* row = IN + ((size_t)(b * I + kb + i)) * NIN;
            sB[i][q4 + 0] = row[sSrc[q4 + 0]];
            sB[i][q4 + 1] = row[sSrc[q4 + 1]];
            sB[i][q4 + 2] = row[sSrc[q4 + 2]];
            sB[i][q4 + 3] = row[sSrc[q4 + 3]];
        } else {
            int qq = tid >> 1, i4 = (tid & 1) * 4;
            float4 v = *(const float4*)(IN + ((size_t)(b * QOUT + q0 + qq)) * I + kb + i4);
            sB[i4 + 0][qq] = v.x; sB[i4 + 1][qq] = v.y;
            sB[i4 + 2][qq] = v.z; sB[i4 + 3][qq] = v.w;
        }
        __syncthreads();
#pragma unroll
        for (int kk = 0; kk < 8; kk++) {
            float a[8], bf[8];
            *(float4*)&a[0]  = *(const float4*)&sA[kk][ty * 8];
            *(float4*)&a[4]  = *(const float4*)&sA[kk][ty * 8 + 4];
            *(float4*)&bf[0] = *(const float4*)&sB[kk][tx * 8];
            *(float4*)&bf[4] = *(const float4*)&sB[kk][tx * 8 + 4];
#pragma unroll
            for (int i = 0; i < 8; i++)
#pragma unroll
                for (int j = 0; j < 8; j++) acc[i][j] = fmaf(a[i], bf[j], acc[i][j]);
        }
        __syncthreads();
    }
#pragma unroll
    for (int i = 0; i < 8; i++) {
        float bv = bias[o0 + ty * 8 + i];
        float* orow = OUT + ((size_t)(b * O + o0 + ty * 8 + i)) * QOUT + q0 + tx * 8;
#pragma unroll
        for (int j = 0; j < 8; j++) orow[j] = acc[i][j] + bv;
    }
}

// ---------------- BN stats: one block per channel, deterministic tree reduce ------
__global__ void __launch_bounds__(256) bn_stats_kernel(const float* __restrict__ x,
                                                       const float* __restrict__ gam,
                                                       const float* __restrict__ bet,
                                                       int Q) {
    int c = blockIdx.x, Ch = gridDim.x, tid = threadIdx.x;
    float s = 0.f, s2 = 0.f;
    for (int b = 0; b < BB; b++) {
        const float* p = x + ((size_t)(b * Ch + c)) * Q;
        for (int q = tid; q < Q; q += 256) { float v = p[q]; s += v; s2 = fmaf(v, v, s2); }
    }
    __shared__ float sh1[256], sh2[256];
    sh1[tid] = s; sh2[tid] = s2; __syncthreads();
    for (int st = 128; st > 0; st >>= 1) {
        if (tid < st) { sh1[tid] += sh1[tid + st]; sh2[tid] += sh2[tid + st]; }
        __syncthreads();
    }
    if (tid == 0) {
        float M = (float)BB * (float)Q;
        float mean = sh1[0] / M;
        float var  = sh2[0] / M - mean * mean;
        float sc   = gam[c] * rsqrtf(var + 1e-5f);
        g_scale[c] = sc;
        g_shift[c] = bet[c] - mean * sc;
    }
}

// ---------------- apply kernels ----------------
__global__ void __launch_bounds__(256) bn_relu_x1_kernel(float* __restrict__ x) {
    int i = blockIdx.x * 256 + threadIdx.x;            // [B,128,2048]
    int c = (i >> 11) & 127;
    x[i] = fmaxf(fmaf(x[i], g_scale[c], g_shift[c]), 0.f);
}

__global__ void __launch_bounds__(256) dsg_max_kernel(const float* __restrict__ h,
                                                      float* __restrict__ x2) {
    int i = blockIdx.x * 256 + threadIdx.x;            // [B,128,2048]
    int c = (i >> 11) & 127;
    float s = g_scale[c], t = g_shift[c];
    const float4* p = reinterpret_cast<const float4*>(h) + (size_t)i * 2;
    float4 v0 = p[0], v1 = p[1];
    float m = fmaf(v0.x, s, t);
    m = fmaxf(m, fmaf(v0.y, s, t)); m = fmaxf(m, fmaf(v0.z, s, t));
    m = fmaxf(m, fmaf(v0.w, s, t)); m = fmaxf(m, fmaf(v1.x, s, t));
    m = fmaxf(m, fmaf(v1.y, s, t)); m = fmaxf(m, fmaf(v1.z, s, t));
    m = fmaxf(m, fmaf(v1.w, s, t));
    x2[i] = fmaxf(m, 0.f);
}

__global__ void __launch_bounds__(256) lap_kernel(const float* __restrict__ x2,
                                                  const int* __restrict__ idx,
                                                  float* __restrict__ lap) {
    int b  = blockIdx.x >> 6;
    int n0 = (blockIdx.x & 63) << 5;
    int tid = threadIdx.x;
    __shared__ float sx[32][129];
    for (int i = tid; i < 4096; i += 256) {            // stage x2[b,:,n0:n0+32]
        int r = i >> 5, nl = i & 31;
        sx[nl][r] = x2[((size_t)(b * RR + r)) * NN + n0 + nl];
    }
    __syncthreads();
    const int*   ib = idx + (size_t)b * NN * KK;
    const float* xb = x2 + (size_t)b * RR * NN;
    for (int it = tid; it < 4096; it += 256) {
        int nl = it >> 7, r2 = it & 127;
        int n2 = n0 + nl;
        int fbase = (n2 << 11) + r2;
        float sum = 0.f;
#pragma unroll
        for (int j2 = 0; j2 < 16; j2++) {
            int f = fbase + (j2 << 7);
            int r = f >> 15;
            int p = f & 32767;                         // flat idx offset == p (K=16)
            int s = ib[p];
            sum += xb[(size_t)(r << 11) + s];
        }
        lap[((size_t)(b * NN + n2)) * RR + r2] = sx[nl][r2] - sum * 0.0625f;
    }
}

__global__ void __launch_bounds__(256) add_relu_kernel(float* __restrict__ x2,
                                                       const float* __restrict__ t) {
    int i = blockIdx.x * 256 + threadIdx.x;
    int c = (i >> 11) & 127;
    x2[i] += fmaxf(fmaf(t[i], g_scale[c], g_shift[c]), 0.f);
}

__global__ void __launch_bounds__(256) res_kernel(float* __restrict__ y,
                                                  const float* __restrict__ feat) {
    int i = blockIdx.x * 256 + threadIdx.x;            // [B,256,2048]
    int c = (i >> 11) & 255;
    y[i] = fmaxf(fmaf(y[i], g_scale[c], g_shift[c]), 0.f) + feat[i];
}

__global__ void __launch_bounds__(256) final_kernel(float* __restrict__ o) {
    int i = blockIdx.x * 256 + threadIdx.x;            // [B,512,2048]
    int c = (i >> 11) & 511;
    o[i] = fmaxf(fmaf(o[i], g_scale[c], g_shift[c]), 0.f);
}

// ---------------- launch ----------------
extern "C" void kernel_launch(void* const* d_in, const int* in_sizes, int n_in,
                              void* d_out, int out_size) {
    const float* xyz   = (const float*)d_in[0];
    const float* feat  = (const float*)d_in[1];
    const float* w1    = (const float*)d_in[2];
    const float* b1    = (const float*)d_in[3];
    const float* bn1_g = (const float*)d_in[4];
    const float* bn1_b = (const float*)d_in[5];
    const float* fc_w  = (const float*)d_in[6];
    const float* fc_b  = (const float*)d_in[7];
    const float* bng_g = (const float*)d_in[8];
    const float* bng_b = (const float*)d_in[9];
    const float* lu_w  = (const float*)d_in[10];
    const float* lu_b  = (const float*)d_in[11];
    const float* bnl_g = (const float*)d_in[12];
    const float* bnl_b = (const float*)d_in[13];
    const float* w2    = (const float*)d_in[14];
    const float* b2    = (const float*)d_in[15];
    const float* bn2_g = (const float*)d_in[16];
    const float* bn2_b = (const float*)d_in[17];
    const float* w3    = (const float*)d_in[18];
    const float* b3    = (const float*)d_in[19];
    const float* bn3_g = (const float*)d_in[20];
    const float* bn3_b = (const float*)d_in[21];
    float* out = (float*)d_out;

    float *x1, *x2, *h, *lap, *t, *y; int* idxp;
    cudaGetSymbolAddress((void**)&x1,  g_x1);
    cudaGetSymbolAddress((void**)&x2,  g_x2);
    cudaGetSymbolAddress((void**)&h,   g_h);
    cudaGetSymbolAddress((void**)&lap, g_lap);
    cudaGetSymbolAddress((void**)&t,   g_t);
    cudaGetSymbolAddress((void**)&y,   g_y);
    cudaGetSymbolAddress((void**)&idxp, g_idx);

    // 1. kNN (top-16, prefix-8 reused for DSgroup)
    knn_kernel<<<BB * 8, 256>>>(xyz, idxp);

    // 2. mlp1: x1 = w1 @ feat + b1 ; BN stats ; BN+ReLU in place
    gemm_kernel<128, 256, 2048, 2048, 0><<<dim3(16, 1, BB), 256>>>(feat, w1, b1, x1, nullptr);
    bn_stats_kernel<<<128, 256>>>(x1, bn1_g, bn1_b, 2048);
    bn_relu_x1_kernel<<<16384, 256>>>(x1);

    // 3. DSgroupMLP: gathered GEMM -> h ; stats ; fused BN+ReLU+max8 -> x2
    gemm_kernel<128, 128, 16384, 2048, 1><<<dim3(128, 1, BB), 256>>>(x1, fc_w, fc_b, h, idxp);
    bn_stats_kernel<<<128, 256>>>(h, bng_g, bng_b, 16384);
    dsg_max_kernel<<<16384, 256>>>(h, x2);

    // 4. FeatureLaplacian: lap ; t = lu_w @ lap + lu_b ; stats ; x2 += relu(bn(t))
    lap_kernel<<<BB * 64, 256>>>(x2, idxp, lap);
    gemm_kernel<128, 128, 2048, 2048, 2><<<dim3(16, 1, BB), 256>>>(lap, lu_w, lu_b, t, nullptr);
    bn_stats_kernel<<<128, 256>>>(t, bnl_g, bnl_b, 2048);
    add_relu_kernel<<<16384, 256>>>(x2, t);

    // 5. mlp2 + residual feat
    gemm_kernel<256, 128, 2048, 2048, 0><<<dim3(16, 2, BB), 256>>>(x2, w2, b2, y, nullptr);
    bn_stats_kernel<<<256, 256>>>(y, bn2_g, bn2_b, 2048);
    res_kernel<<<32768, 256>>>(y, feat);

    // 6. mlp3 -> out
    gemm_kernel<512, 256, 2048, 2048, 0><<<dim3(16, 4, BB), 256>>>(y, w3, b3, out, nullptr);
    bn_stats_kernel<<<512, 256>>>(out, bn3_g, bn3_b, 2048);
    final_kernel<<<65536, 256>>>(out);
}

// round 5
// speedup vs baseline: 1.1690x; 1.1690x over previous
#include <cuda_runtime.h>

#define BB 16
#define NN 2048
#define CC 256
#define RR 128
#define KK 16

// ---------------- scratch (device globals; no runtime allocation) ----------------
__device__ float g_x1 [BB*RR*NN];          // mlp1 out -> post-BN x
__device__ float g_x2 [BB*RR*NN];          // DSgroup out x (then x+t)
__device__ float g_x2t[BB*NN*RR];          // x2 transposed [b,n,c]
__device__ float g_z  [BB*RR*NN];          // z = fc_w @ x1 (pre-BN h deduped)
__device__ float g_zt [BB*NN*RR];          // z transposed [b,n,c]
__device__ float g_lap[BB*NN*RR];          // laplacian [B,N,R]
__device__ float g_t  [BB*RR*NN];          // lu pre-BN
__device__ float g_y  [BB*CC*NN];          // mlp2 pre-BN -> y
__device__ int   g_idx[BB*NN*KK];          // knn top-16 (sorted)
__device__ int   g_cnt[BB*NN];             // gather multiplicity (first 8 neighbors)
__device__ float g_p1 [512*BB];            // stats partials
__device__ float g_p2 [512*BB];
__device__ float g_scale[512];
__device__ float g_shift[512];

// ---------------- kNN: top-16 by (dist, index), stable -- DO NOT TOUCH -----------
__global__ void __launch_bounds__(256) knn_kernel(const float* __restrict__ xyz,
                                                  int* __restrict__ idx) {
    int b  = blockIdx.x >> 3;
    int q0 = (blockIdx.x & 7) << 8;
    __shared__ float sx[NN], sy[NN], sxx[NN];
    const float* bx = xyz + (size_t)b * 3 * NN;
    for (int i = threadIdx.x; i < NN; i += 256) {
        float xv = bx[i], yv = bx[NN + i];
        sx[i] = xv; sy[i] = yv;
        sxx[i] = __fadd_rn(__fmul_rn(xv, xv), __fmul_rn(yv, yv));
    }
    __syncthreads();
    int q = q0 + threadIdx.x;
    float xq = sx[q], yq = sy[q];
    float xxq = sxx[q];
    float bd[KK]; int bi[KK];
#pragma unroll
    for (int i = 0; i < KK; i++) { bd[i] = 3.4e38f; bi[i] = 0; }
    for (int m = 0; m < NN; m++) {
        float inner = __fmaf_rn(yq, sy[m], __fmul_rn(xq, sx[m]));
        float d = __fadd_rn(__fsub_rn(xxq, __fmul_rn(2.0f, inner)), sxx[m]);
        if (d < bd[KK - 1]) {
            int pos = KK - 1;
            while (pos > 0 && d < bd[pos - 1]) {
                bd[pos] = bd[pos - 1]; bi[pos] = bi[pos - 1]; --pos;
            }
            bd[pos] = d; bi[pos] = m;
        }
    }
    int* o = idx + ((size_t)(b * NN + q)) * KK;
#pragma unroll
    for (int i = 0; i < KK; i++) o[i] = bi[i];
}

// ---------------- pipelined tiled SGEMM --------------------------------------------
// OUT[b,o,q] = W[o,:] . IN[b,:,q] + bias, k ascending (bitwise same as before)
// MODE 0: IN is [B, I, NIN] channel-major;  MODE 2: IN is [B, QOUT, I] position-major
// WT: additionally write OUT_T[b, q, o]
template<int O, int I, int QOUT, int NIN, int MODE, bool WT>
__global__ void __launch_bounds__(256, 2) gemm2_kernel(const float* __restrict__ IN,
                                                       const float* __restrict__ W,
                                                       const float* __restrict__ bias,
                                                       float* __restrict__ OUT,
                                                       float* __restrict__ OUT_T) {
    __shared__ float sA[2][16][128];
    __shared__ float sB[2][16][128];
    int b  = blockIdx.z;
    int q0 = blockIdx.x * 128;
    int o0 = blockIdx.y * 128;
    int tid = threadIdx.x;
    int tx = tid & 15, ty = tid >> 4;

    float4 rA0, rA1, rB0, rB1;
    const int oA = tid >> 1, iA = (tid & 1) * 8;

    // prologue: kb = 0
    rA0 = *(const float4*)(W + (size_t)(o0 + oA) * I + iA);
    rA1 = *(const float4*)(W + (size_t)(o0 + oA) * I + iA + 4);
    if (MODE == 0) {
        int i = tid >> 4, q8 = (tid & 15) * 8;
        const float* p = IN + ((size_t)(b * I + i)) * NIN + q0 + q8;
        rB0 = *(const float4*)p; rB1 = *(const float4*)(p + 4);
    } else {
        int qq = tid >> 1, i8 = (tid & 1) * 8;
        const float* p = IN + ((size_t)(b * QOUT + q0 + qq)) * I + i8;
        rB0 = *(const float4*)p; rB1 = *(const float4*)(p + 4);
    }
    // store prologue to buf 0
    {
        float av[8] = {rA0.x, rA0.y, rA0.z, rA0.w, rA1.x, rA1.y, rA1.z, rA1.w};
#pragma unroll
        for (int t = 0; t < 8; t++) sA[0][iA + t][oA] = av[t];
        if (MODE == 0) {
            int i = tid >> 4, q8 = (tid & 15) * 8;
            *(float4*)&sB[0][i][q8] = rB0; *(float4*)&sB[0][i][q8 + 4] = rB1;
        } else {
            int qq = tid >> 1, i8 = (tid & 1) * 8;
            float bv[8] = {rB0.x, rB0.y, rB0.z, rB0.w, rB1.x, rB1.y, rB1.z, rB1.w};
#pragma unroll
            for (int t = 0; t < 8; t++) sB[0][i8 + t][qq] = bv[t];
        }
    }
    __syncthreads();

    float acc[8][8];
#pragma unroll
    for (int i = 0; i < 8; i++)
#pragma unroll
        for (int j = 0; j < 8; j++) acc[i][j] = 0.f;

    int buf = 0;
    for (int kb = 0; kb < I; kb += 16) {
        bool more = (kb + 16) < I;
        if (more) {
            int kn = kb + 16;
            rA0 = *(const float4*)(W + (size_t)(o0 + oA) * I + kn + iA);
            rA1 = *(const float4*)(W + (size_t)(o0 + oA) * I + kn + iA + 4);
            if (MODE == 0) {
                int i = tid >> 4, q8 = (tid & 15) * 8;
                const float* p = IN + ((size_t)(b * I + kn + i)) * NIN + q0 + q8;
                rB0 = *(const float4*)p; rB1 = *(const float4*)(p + 4);
            } else {
                int qq = tid >> 1, i8 = (tid & 1) * 8;
                const float* p = IN + ((size_t)(b * QOUT + q0 + qq)) * I + kn + i8;
                rB0 = *(const float4*)p; rB1 = *(const float4*)(p + 4);
            }
        }
#pragma unroll
        for (int kk = 0; kk < 16; kk++) {
            float a[8], bf[8];
            *(float4*)&a[0]  = *(const float4*)&sA[buf][kk][ty * 8];
            *(float4*)&a[4]  = *(const float4*)&sA[buf][kk][ty * 8 + 4];
            *(float4*)&bf[0] = *(const float4*)&sB[buf][kk][tx * 8];
            *(float4*)&bf[4] = *(const float4*)&sB[buf][kk][tx * 8 + 4];
#pragma unroll
            for (int i = 0; i < 8; i++)
#pragma unroll
                for (int j = 0; j < 8; j++) acc[i][j] = fmaf(a[i], bf[j], acc[i][j]);
        }
        if (more) {
            int nb = buf ^ 1;
            float av[8] = {rA0.x, rA0.y, rA0.z, rA0.w, rA1.x, rA1.y, rA1.z, rA1.w};
#pragma unroll
            for (int t = 0; t < 8; t++) sA[nb][iA + t][oA] = av[t];
            if (MODE == 0) {
                int i = tid >> 4, q8 = (tid & 15) * 8;
                *(float4*)&sB[nb][i][q8] = rB0; *(float4*)&sB[nb][i][q8 + 4] = rB1;
            } else {
                int qq = tid >> 1, i8 = (tid & 1) * 8;
                float bv[8] = {rB0.x, rB0.y, rB0.z, rB0.w, rB1.x, rB1.y, rB1.z, rB1.w};
#pragma unroll
                for (int t = 0; t < 8; t++) sB[nb][i8 + t][qq] = bv[t];
            }
        }
        __syncthreads();
        buf ^= 1;
    }
    // epilogue
    float bv[8];
#pragma unroll
    for (int i = 0; i < 8; i++) bv[i] = bias[o0 + ty * 8 + i];
#pragma unroll
    for (int i = 0; i < 8; i++) {
        float* orow = OUT + ((size_t)(b * O + o0 + ty * 8 + i)) * QOUT + q0 + tx * 8;
        float4 v0 = {acc[i][0] + bv[i], acc[i][1] + bv[i], acc[i][2] + bv[i], acc[i][3] + bv[i]};
        float4 v1 = {acc[i][4] + bv[i], acc[i][5] + bv[i], acc[i][6] + bv[i], acc[i][7] + bv[i]};
        *(float4*)orow = v0; *(float4*)(orow + 4) = v1;
    }
    if (WT) {
#pragma unroll
        for (int j = 0; j < 8; j++) {
            float* trow = OUT_T + ((size_t)(b * QOUT + q0 + tx * 8 + j)) * O + o0 + ty * 8;
            float4 v0 = {acc[0][j] + bv[0], acc[1][j] + bv[1], acc[2][j] + bv[2], acc[3][j] + bv[3]};
            float4 v1 = {acc[4][j] + bv[4], acc[5][j] + bv[5], acc[6][j] + bv[6], acc[7][j] + bv[7]};
            *(float4*)trow = v0; *(float4*)(trow + 4) = v1;
        }
    }
}

// ---------------- BN stats: per-(channel,batch) partials, then finalize -----------
__global__ void __launch_bounds__(256) bn_part_kernel(const float* __restrict__ x,
                                                      const int* __restrict__ cnt,
                                                      int Q) {
    int c = blockIdx.x, b = blockIdx.y, Ch = gridDim.x, tid = threadIdx.x;
    const float* p = x + ((size_t)(b * Ch + c)) * Q;
    const int* cb = cnt ? cnt + b * Q : nullptr;
    float s = 0.f, s2 = 0.f;
    for (int q = tid; q < Q; q += 256) {
        float v = p[q];
        float w = cb ? (float)cb[q] : 1.f;
        float wv = w * v;
        s += wv; s2 = fmaf(wv, v, s2);
    }
    __shared__ float sh1[256], sh2[256];
    sh1[tid] = s; sh2[tid] = s2; __syncthreads();
    for (int st = 128; st > 0; st >>= 1) {
        if (tid < st) { sh1[tid] += sh1[tid + st]; sh2[tid] += sh2[tid + st]; }
        __syncthreads();
    }
    if (tid == 0) { g_p1[c * BB + b] = sh1[0]; g_p2[c * BB + b] = sh2[0]; }
}

__global__ void bn_fin_kernel(const float* __restrict__ gam,
                              const float* __restrict__ bet, float M) {
    int c = blockIdx.x;
    if (threadIdx.x == 0) {
        float s = 0.f, s2 = 0.f;
        for (int b = 0; b < BB; b++) { s += g_p1[c * BB + b]; s2 += g_p2[c * BB + b]; }
        float mean = s / M;
        float var  = s2 / M - mean * mean;
        float sc   = gam[c] * rsqrtf(var + 1e-5f);
        g_scale[c] = sc;
        g_shift[c] = bet[c] - mean * sc;
    }
}

// ---------------- gather multiplicity (first 8 neighbors) -------------------------
__global__ void __launch_bounds__(256) cnt_kernel(const int* __restrict__ idx,
                                                  int* __restrict__ cnt) {
    int b = blockIdx.x, tid = threadIdx.x;
    __shared__ int sc[NN];
    for (int i = tid; i < NN; i += 256) sc[i] = 0;
    __syncthreads();
    for (int i = tid; i < NN * 8; i += 256) {
        int n = i >> 3, j = i & 7;
        atomicAdd(&sc[idx[((size_t)(b * NN + n)) * KK + j]], 1);
    }
    __syncthreads();
    for (int i = tid; i < NN; i += 256) cnt[b * NN + i] = sc[i];
}

// ---------------- DSgroup: gather z_t rows, BN+max8+ReLU, write x2 & x2_t --------
__global__ void __launch_bounds__(256) dsg_max_kernel(const float* __restrict__ zt,
                                                      const int* __restrict__ idx,
                                                      float* __restrict__ x2,
                                                      float* __restrict__ x2t) {
    int b = blockIdx.y, n0 = blockIdx.x * 32;
    int tid = threadIdx.x, w = tid >> 5, lane = tid & 31;
    __shared__ float stage[32][129];
    const float4* scv = (const float4*)g_scale;
    const float4* shv = (const float4*)g_shift;
    float4 sc = scv[lane], sh = shv[lane];
#pragma unroll
    for (int phase = 0; phase < 4; phase++) {
        int nl = phase * 8 + w;
        int n  = n0 + nl;
        int src = 0;
        if (lane < 8) {
            int p = lane * NN + n;                           // scrambled view position
            src = idx[((size_t)(b * NN + (p >> 3))) * KK + (p & 7)];
        }
        float4 m;
#pragma unroll
        for (int j = 0; j < 8; j++) {
            int s = __shfl_sync(0xffffffffu, src, j);
            float4 v = *(const float4*)(zt + ((size_t)(b * NN + s)) * RR + lane * 4);
            float4 t;
            t.x = fmaf(v.x, sc.x, sh.x); t.y = fmaf(v.y, sc.y, sh.y);
            t.z = fmaf(v.z, sc.z, sh.z); t.w = fmaf(v.w, sc.w, sh.w);
            if (j == 0) m = t;
            else {
                m.x = fmaxf(m.x, t.x); m.y = fmaxf(m.y, t.y);
                m.z = fmaxf(m.z, t.z); m.w = fmaxf(m.w, t.w);
            }
        }
        stage[nl][lane * 4 + 0] = fmaxf(m.x, 0.f);
        stage[nl][lane * 4 + 1] = fmaxf(m.y, 0.f);
        stage[nl][lane * 4 + 2] = fmaxf(m.z, 0.f);
        stage[nl][lane * 4 + 3] = fmaxf(m.w, 0.f);
    }
    __syncthreads();
    for (int i = tid; i < 4096; i += 256) {                  // x2 [b,c,n]
        int c = i >> 5, nl = i & 31;
        x2[((size_t)(b * RR + c)) * NN + n0 + nl] = stage[nl][c];
    }
    for (int i = tid; i < 4096; i += 256) {                  // x2_t [b,n,c]
        int nl = i >> 7, c = i & 127;
        x2t[((size_t)(b * NN + n0 + nl)) * RR + c] = stage[nl][c];
    }
}

// ---------------- Laplacian: smem-staged single channel row per block -------------
__global__ void __launch_bounds__(256) lap_kernel(const float* __restrict__ x2,
                                                  const float* __restrict__ x2t,
                                                  const int* __restrict__ idx,
                                                  float* __restrict__ lap) {
    int g = blockIdx.x, b = blockIdx.y, tid = threadIdx.x;
    __shared__ float srow[NN];
    const float4* src4 = (const float4*)(x2 + ((size_t)(b * RR + g)) * NN);
    for (int i = tid; i < NN / 4; i += 256) ((float4*)srow)[i] = src4[i];
    __syncthreads();
    const int* ib = idx + (size_t)b * NN * KK;
    for (int it = tid; it < 2048; it += 256) {
        int nl = it >> 7, r2 = it & 127;
        int base = nl * NN + r2;                             // p = f - g*32768
        float sum = 0.f;
#pragma unroll
        for (int j = 0; j < 16; j++) sum += srow[ib[base + (j << 7)]];
        int n = g * 16 + nl;
        size_t o = ((size_t)(b * NN + n)) * RR + r2;
        lap[o] = x2t[o] - sum * 0.0625f;
    }
}

// ---------------- elementwise (float4) ----------------
__global__ void __launch_bounds__(256) bn_relu_x1_kernel(float* __restrict__ x) {
    int i = blockIdx.x * 256 + threadIdx.x;
    int c = (i >> 9) & 127;
    float s = g_scale[c], t = g_shift[c];
    float4 v = ((float4*)x)[i];
    v.x = fmaxf(fmaf(v.x, s, t), 0.f); v.y = fmaxf(fmaf(v.y, s, t), 0.f);
    v.z = fmaxf(fmaf(v.z, s, t), 0.f); v.w = fmaxf(fmaf(v.w, s, t), 0.f);
    ((float4*)x)[i] = v;
}

__global__ void __launch_bounds__(256) add_relu_kernel(float* __restrict__ x2,
                                                       const float* __restrict__ t) {
    int i = blockIdx.x * 256 + threadIdx.x;
    int c = (i >> 9) & 127;
    float s = g_scale[c], sh = g_shift[c];
    float4 v = ((const float4*)t)[i];
    float4 o = ((float4*)x2)[i];
    o.x += fmaxf(fmaf(v.x, s, sh), 0.f); o.y += fmaxf(fmaf(v.y, s, sh), 0.f);
    o.z += fmaxf(fmaf(v.z, s, sh), 0.f); o.w += fmaxf(fmaf(v.w, s, sh), 0.f);
    ((float4*)x2)[i] = o;
}

__global__ void __launch_bounds__(256) res_kernel(float* __restrict__ y,
                                                  const float* __restrict__ feat) {
    int i = blockIdx.x * 256 + threadIdx.x;
    int c = (i >> 9) & 255;
    float s = g_scale[c], t = g_shift[c];
    float4 v = ((float4*)y)[i];
    float4 f = ((const float4*)feat)[i];
    v.x = fmaxf(fmaf(v.x, s, t), 0.f) + f.x; v.y = fmaxf(fmaf(v.y, s, t), 0.f) + f.y;
    v.z = fmaxf(fmaf(v.z, s, t), 0.f) + f.z; v.w = fmaxf(fmaf(v.w, s, t), 0.f) + f.w;
    ((float4*)y)[i] = v;
}

__global__ void __launch_bounds__(256) final_kernel(float* __restrict__ o) {
    int i = blockIdx.x * 256 + threadIdx.x;
    int c = (i >> 9) & 511;
    float s = g_scale[c], t = g_shift[c];
    float4 v = ((float4*)o)[i];
    v.x = fmaxf(fmaf(v.x, s, t), 0.f); v.y = fmaxf(fmaf(v.y, s, t), 0.f);
    v.z = fmaxf(fmaf(v.z, s, t), 0.f); v.w = fmaxf(fmaf(v.w, s, t), 0.f);
    ((float4*)o)[i] = v;
}

// ---------------- launch ----------------
extern "C" void kernel_launch(void* const* d_in, const int* in_sizes, int n_in,
                              void* d_out, int out_size) {
    const float* xyz   = (const float*)d_in[0];
    const float* feat  = (const float*)d_in[1];
    const float* w1    = (const float*)d_in[2];
    const float* b1    = (const float*)d_in[3];
    const float* bn1_g = (const float*)d_in[4];
    const float* bn1_b = (const float*)d_in[5];
    const float* fc_w  = (const float*)d_in[6];
    const float* fc_b  = (const float*)d_in[7];
    const float* bng_g = (const float*)d_in[8];
    const float* bng_b = (const float*)d_in[9];
    const float* lu_w  = (const float*)d_in[10];
    const float* lu_b  = (const float*)d_in[11];
    const float* bnl_g = (const float*)d_in[12];
    const float* bnl_b = (const float*)d_in[13];
    const float* w2    = (const float*)d_in[14];
    const float* b2    = (const float*)d_in[15];
    const float* bn2_g = (const float*)d_in[16];
    const float* bn2_b = (const float*)d_in[17];
    const float* w3    = (const float*)d_in[18];
    const float* b3    = (const float*)d_in[19];
    const float* bn3_g = (const float*)d_in[20];
    const float* bn3_b = (const float*)d_in[21];
    float* out = (float*)d_out;

    float *x1, *x2, *x2t, *z, *zt, *lap, *t, *y; int *idxp, *cntp;
    cudaGetSymbolAddress((void**)&x1,  g_x1);
    cudaGetSymbolAddress((void**)&x2,  g_x2);
    cudaGetSymbolAddress((void**)&x2t, g_x2t);
    cudaGetSymbolAddress((void**)&z,   g_z);
    cudaGetSymbolAddress((void**)&zt,  g_zt);
    cudaGetSymbolAddress((void**)&lap, g_lap);
    cudaGetSymbolAddress((void**)&t,   g_t);
    cudaGetSymbolAddress((void**)&y,   g_y);
    cudaGetSymbolAddress((void**)&idxp, g_idx);
    cudaGetSymbolAddress((void**)&cntp, g_cnt);

    // 1. kNN + gather counts
    knn_kernel<<<BB * 8, 256>>>(xyz, idxp);
    cnt_kernel<<<BB, 256>>>(idxp, cntp);

    // 2. mlp1
    gemm2_kernel<128, 256, 2048, 2048, 0, false><<<dim3(16, 1, BB), 256>>>(feat, w1, b1, x1, nullptr);
    bn_part_kernel<<<dim3(128, BB), 256>>>(x1, nullptr, 2048);
    bn_fin_kernel<<<128, 32>>>(bn1_g, bn1_b, (float)(BB * 2048));
    bn_relu_x1_kernel<<<4096, 256>>>(x1);

    // 3. DSgroupMLP (deduped): z = fc_w@x1+fc_b; weighted stats; gather+BN+max8
    gemm2_kernel<128, 128, 2048, 2048, 0, true><<<dim3(16, 1, BB), 256>>>(x1, fc_w, fc_b, z, zt);
    bn_part_kernel<<<dim3(128, BB), 256>>>(z, cntp, 2048);
    bn_fin_kernel<<<128, 32>>>(bng_g, bng_b, (float)(BB * 16384));
    dsg_max_kernel<<<dim3(64, BB), 256>>>(zt, idxp, x2, x2t);

    // 4. FeatureLaplacian
    lap_kernel<<<dim3(128, BB), 256>>>(x2, x2t, idxp, lap);
    gemm2_kernel<128, 128, 2048, 2048, 2, false><<<dim3(16, 1, BB), 256>>>(lap, lu_w, lu_b, t, nullptr);
    bn_part_kernel<<<dim3(128, BB), 256>>>(t, nullptr, 2048);
    bn_fin_kernel<<<128, 32>>>(bnl_g, bnl_b, (float)(BB * 2048));
    add_relu_kernel<<<4096, 256>>>(x2, t);

    // 5. mlp2 + residual
    gemm2_kernel<256, 128, 2048, 2048, 0, false><<<dim3(16, 2, BB), 256>>>(x2, w2, b2, y, nullptr);
    bn_part_kernel<<<dim3(256, BB), 256>>>(y, nullptr, 2048);
    bn_fin_kernel<<<256, 32>>>(bn2_g, bn2_b, (float)(BB * 2048));
    res_kernel<<<8192, 256>>>(y, feat);

    // 6. mlp3 -> out
    gemm2_kernel<512, 256, 2048, 2048, 0, false><<<dim3(16, 4, BB), 256>>>(y, w3, b3, out, nullptr);
    bn_part_kernel<<<dim3(512, BB), 256>>>(out, nullptr, 2048);
    bn_fin_kernel<<<512, 32>>>(bn3_g, bn3_b, (float)(BB * 2048));
    final_kernel<<<16384, 256>>>(out);
}